// round 14
// baseline (speedup 1.0000x reference)
#include <cuda_runtime.h>
#include <cuda_bf16.h>

// PearsonLoss: x1 [8,32,256,256] f32, x2 same, margin [8,256,256] i32 -> scalar f32
//
// Streaming formulation over C=32 channels (no probability storage):
//   e1=exp(x1), e2=exp(x2); S1,S2,S11,S22,S12 running sums.
//   EX=EY=1/C exactly (softmax sums to 1).
//   score = (S12/(S1*S2*C) - 1/C^2) / sqrt((S11/(S1^2 C)-1/C^2)(S22/(S2^2 C)-1/C^2))
//   per_pixel = margin==0 ? 1-score : max(score,0);  out = mean.
//
// R14: L2 BULK PREFETCH. Nine measurements show the ~5.1TB/s plateau is
// invariant to every SM-side issue knob (occupancy, MLP, block shape, load
// width, desync, .ca/.cs/.cv). Remaining Little's-law lever: cut the SERVICE
// LATENCY. cp.async.bulk.prefetch.L2.global (bulk engine, fire-and-forget,
// no scoreboard/smem/barriers) pulls each block's next channels into L2 so
// demand LDGs hit L2 (~250cyc) instead of DRAM (~600cyc).
//  - Hot loop: exact R1 measured-best shape (256thr, 4px/thread float4,
//    grid 512). Threads 0/1 prefetch channel c+6 of x1/x2 (4KB each: a
//    block's slice per channel is 1024px*4B, contiguous, 4KB-aligned).
//  - Prologue prefetches channels 0..5. Single-launch finalize.

#define C_CH   32
#define HW     65536          // 256*256
#define NBATCH 8
#define NPIX   (NBATCH * HW)  // 524288
#define PIX_PER_THREAD 4
#define NTHREADS_TOTAL (NPIX / PIX_PER_THREAD)  // 131072
#define BLOCK_SIZE 256
#define NBLOCKS (NTHREADS_TOTAL / BLOCK_SIZE)   // 512
#define PF_DIST  6
#define PF_BYTES (BLOCK_SIZE * PIX_PER_THREAD * 4)   // 4096: block slice/channel

__device__ float        g_acc   = 0.0f;
__device__ unsigned int g_count = 0u;

__device__ __forceinline__ void l2_prefetch(const void* p) {
    asm volatile("cp.async.bulk.prefetch.L2.global [%0], %1;"
                 :: "l"(p), "r"((unsigned)PF_BYTES));
}

__device__ __forceinline__ float finalize_pixel(float s1, float s2,
                                                float s11, float s22, float s12,
                                                int m) {
    const float invC  = 1.0f / 32.0f;
    const float invC2 = invC * invC;
    float r1 = __frcp_rn(s1);
    float r2 = __frcp_rn(s2);
    float vx  = fmaf(s11 * r1 * r1, invC, -invC2);   // EX2 - EX^2
    float vy  = fmaf(s22 * r2 * r2, invC, -invC2);   // EY2 - EY^2
    float num = fmaf(s12 * r1 * r2, invC, -invC2);   // EXY - EX*EY
    float score = num * rsqrtf(vx * vy);
    return (m == 0) ? (1.0f - score) : fmaxf(score, 0.0f);
}

__global__ void __launch_bounds__(BLOCK_SIZE)
pearson_loss_kernel(const float* __restrict__ x1,
                    const float* __restrict__ x2,
                    const int*   __restrict__ margin,
                    float* __restrict__ out) {
    const int t  = blockIdx.x * BLOCK_SIZE + threadIdx.x;  // 0..131071
    const int p0 = t * PIX_PER_THREAD;                     // base pixel
    const int b  = p0 >> 16;                               // / HW
    const int hw = p0 & (HW - 1);

    const float4* __restrict__ x1p =
        (const float4*)(x1 + (size_t)b * C_CH * HW + hw);
    const float4* __restrict__ x2p =
        (const float4*)(x2 + (size_t)b * C_CH * HW + hw);
    const int cstride4 = HW / 4;   // float4 stride per channel

    // Block-level base of this block's 4KB-per-channel slice.
    const int pb       = blockIdx.x * BLOCK_SIZE * PIX_PER_THREAD; // block base px
    const int bb       = pb >> 16;
    const int hwb      = pb & (HW - 1);
    const float* base1 = x1 + (size_t)bb * C_CH * HW + hwb;
    const float* base2 = x2 + (size_t)bb * C_CH * HW + hwb;

    // Prologue: prefetch channels 0..PF_DIST-1 (threads 0/1 split tensors).
    if (threadIdx.x < 2) {
        const float* bse = (threadIdx.x == 0) ? base1 : base2;
#pragma unroll
        for (int c = 0; c < PF_DIST; c++)
            l2_prefetch(bse + (size_t)c * HW);
    }

    float4 S1  = make_float4(0.f, 0.f, 0.f, 0.f);
    float4 S2  = make_float4(0.f, 0.f, 0.f, 0.f);
    float4 S11 = make_float4(0.f, 0.f, 0.f, 0.f);
    float4 S22 = make_float4(0.f, 0.f, 0.f, 0.f);
    float4 S12 = make_float4(0.f, 0.f, 0.f, 0.f);

#pragma unroll 8
    for (int c = 0; c < C_CH; c++) {
        // Prefetch channel c+PF_DIST while computing channel c.
        if (threadIdx.x < 2 && c + PF_DIST < C_CH) {
            const float* bse = (threadIdx.x == 0) ? base1 : base2;
            l2_prefetch(bse + (size_t)(c + PF_DIST) * HW);
        }

        float4 a = __ldg(&x1p[c * cstride4]);
        float4 v = __ldg(&x2p[c * cstride4]);

        float e1, e2;
        e1 = __expf(a.x); e2 = __expf(v.x);
        S1.x += e1; S2.x += e2;
        S11.x = fmaf(e1, e1, S11.x); S22.x = fmaf(e2, e2, S22.x);
        S12.x = fmaf(e1, e2, S12.x);

        e1 = __expf(a.y); e2 = __expf(v.y);
        S1.y += e1; S2.y += e2;
        S11.y = fmaf(e1, e1, S11.y); S22.y = fmaf(e2, e2, S22.y);
        S12.y = fmaf(e1, e2, S12.y);

        e1 = __expf(a.z); e2 = __expf(v.z);
        S1.z += e1; S2.z += e2;
        S11.z = fmaf(e1, e1, S11.z); S22.z = fmaf(e2, e2, S22.z);
        S12.z = fmaf(e1, e2, S12.z);

        e1 = __expf(a.w); e2 = __expf(v.w);
        S1.w += e1; S2.w += e2;
        S11.w = fmaf(e1, e1, S11.w); S22.w = fmaf(e2, e2, S22.w);
        S12.w = fmaf(e1, e2, S12.w);
    }

    const int4 mg = __ldg(&((const int4*)margin)[t]);

    float local = finalize_pixel(S1.x, S2.x, S11.x, S22.x, S12.x, mg.x)
                + finalize_pixel(S1.y, S2.y, S11.y, S22.y, S12.y, mg.y)
                + finalize_pixel(S1.z, S2.z, S11.z, S22.z, S12.z, mg.z)
                + finalize_pixel(S1.w, S2.w, S11.w, S22.w, S12.w, mg.w);

    // warp reduce
#pragma unroll
    for (int off = 16; off > 0; off >>= 1)
        local += __shfl_xor_sync(0xFFFFFFFF, local, off);

    __shared__ float warp_sums[BLOCK_SIZE / 32];
    const int lane = threadIdx.x & 31;
    const int wid  = threadIdx.x >> 5;
    if (lane == 0) warp_sums[wid] = local;
    __syncthreads();

    __shared__ bool is_last;
    if (threadIdx.x == 0) {
        float s = warp_sums[0];
#pragma unroll
        for (int w = 1; w < BLOCK_SIZE / 32; w++) s += warp_sums[w];
        atomicAdd(&g_acc, s);
        __threadfence();
        unsigned prev = atomicAdd(&g_count, 1u);
        is_last = (prev == (unsigned)(NBLOCKS - 1));
    }
    __syncthreads();

    if (is_last && threadIdx.x == 0) {
        __threadfence();  // make all g_acc contributions visible
        float total = *((volatile float*)&g_acc);
        out[0] = total * (1.0f / (float)NPIX);
        // reset for next graph replay (deterministic relaunch)
        g_acc   = 0.0f;
        g_count = 0u;
    }
}

extern "C" void kernel_launch(void* const* d_in, const int* in_sizes, int n_in,
                              void* d_out, int out_size) {
    const float* x1     = (const float*)d_in[0];
    const float* x2     = (const float*)d_in[1];
    const int*   margin = (const int*)d_in[2];
    float* out = (float*)d_out;

    pearson_loss_kernel<<<NBLOCKS, BLOCK_SIZE>>>(x1, x2, margin, out);
}

// round 15
// speedup vs baseline: 1.2026x; 1.2026x over previous
#include <cuda_runtime.h>
#include <cuda_bf16.h>

// PearsonLoss: x1 [8,32,256,256] f32, x2 same, margin [8,256,256] i32 -> scalar f32
//
// FINAL (R15 lock-in = R5 verbatim, best measured: 28.13us bench).
//
// Streaming formulation over C=32 channels (no probability storage):
//   e1=exp(x1), e2=exp(x2); S1,S2,S11,S22,S12 running sums.
//   EX=EY=1/C exactly (softmax sums to 1).
//   score = (S12/(S1*S2*C) - 1/C^2) / sqrt((S11/(S1^2 C)-1/C^2)(S22/(S2^2 C)-1/C^2))
//   per_pixel = margin==0 ? 1-score : max(score,0);  out = mean.
//
// Session evidence (10 measurements): the ~5.2TB/s DRAM plateau is invariant
// to occupancy (up 2x / down 3.5x), MLP batching, block shape, channel-order
// desync, and cache flavor (.ca/.cs/.cv); narrower loads, smem pipelining,
// and L2 prefetch all regressed (2x / +40% / +17%). ~28.1us bench is this
// workload's floor on this part. Locking the best measured variant:
//  - BLOCK=128, 4px/thread, grid 1024; group-of-4-channel batched float4
//    __ldcs loads; launch_bounds(128,7).
//  - Single launch; last-block-done finalize via __device__ globals, reset
//    by the final block for deterministic graph replay.

#define C_CH   32
#define HW     65536          // 256*256
#define NBATCH 8
#define NPIX   (NBATCH * HW)  // 524288
#define PIX_PER_THREAD 4
#define NTHREADS_TOTAL (NPIX / PIX_PER_THREAD)  // 131072
#define BLOCK_SIZE 128
#define NBLOCKS (NTHREADS_TOTAL / BLOCK_SIZE)   // 1024
#define CH_GROUP 4
#define N_GROUPS (C_CH / CH_GROUP)              // 8

__device__ float        g_acc   = 0.0f;
__device__ unsigned int g_count = 0u;

__device__ __forceinline__ float finalize_pixel(float s1, float s2,
                                                float s11, float s22, float s12,
                                                int m) {
    const float invC  = 1.0f / 32.0f;
    const float invC2 = invC * invC;
    float r1 = __frcp_rn(s1);
    float r2 = __frcp_rn(s2);
    float vx  = fmaf(s11 * r1 * r1, invC, -invC2);   // EX2 - EX^2
    float vy  = fmaf(s22 * r2 * r2, invC, -invC2);   // EY2 - EY^2
    float num = fmaf(s12 * r1 * r2, invC, -invC2);   // EXY - EX*EY
    float score = num * rsqrtf(vx * vy);
    return (m == 0) ? (1.0f - score) : fmaxf(score, 0.0f);
}

__global__ void __launch_bounds__(BLOCK_SIZE, 7)
pearson_loss_kernel(const float* __restrict__ x1,
                    const float* __restrict__ x2,
                    const int*   __restrict__ margin,
                    float* __restrict__ out) {
    const int t  = blockIdx.x * BLOCK_SIZE + threadIdx.x;  // 0..131071
    const int p0 = t * PIX_PER_THREAD;                     // base pixel
    const int b  = p0 >> 16;                               // / HW
    const int hw = p0 & (HW - 1);

    const float4* __restrict__ x1p =
        (const float4*)(x1 + (size_t)b * C_CH * HW + hw);
    const float4* __restrict__ x2p =
        (const float4*)(x2 + (size_t)b * C_CH * HW + hw);
    const int cstride4 = HW / 4;   // float4 stride per channel

    float4 S1  = make_float4(0.f, 0.f, 0.f, 0.f);
    float4 S2  = make_float4(0.f, 0.f, 0.f, 0.f);
    float4 S11 = make_float4(0.f, 0.f, 0.f, 0.f);
    float4 S22 = make_float4(0.f, 0.f, 0.f, 0.f);
    float4 S12 = make_float4(0.f, 0.f, 0.f, 0.f);

#pragma unroll
    for (int g = 0; g < N_GROUPS; g++) {
        // Batch-issue all 8 loads of this group before any compute.
        float4 a[CH_GROUP], v[CH_GROUP];
#pragma unroll
        for (int j = 0; j < CH_GROUP; j++) {
            const int c = g * CH_GROUP + j;
            a[j] = __ldcs(&x1p[c * cstride4]);
            v[j] = __ldcs(&x2p[c * cstride4]);
        }
#pragma unroll
        for (int j = 0; j < CH_GROUP; j++) {
            float e1, e2;
            e1 = __expf(a[j].x); e2 = __expf(v[j].x);
            S1.x += e1; S2.x += e2;
            S11.x = fmaf(e1, e1, S11.x); S22.x = fmaf(e2, e2, S22.x);
            S12.x = fmaf(e1, e2, S12.x);

            e1 = __expf(a[j].y); e2 = __expf(v[j].y);
            S1.y += e1; S2.y += e2;
            S11.y = fmaf(e1, e1, S11.y); S22.y = fmaf(e2, e2, S22.y);
            S12.y = fmaf(e1, e2, S12.y);

            e1 = __expf(a[j].z); e2 = __expf(v[j].z);
            S1.z += e1; S2.z += e2;
            S11.z = fmaf(e1, e1, S11.z); S22.z = fmaf(e2, e2, S22.z);
            S12.z = fmaf(e1, e2, S12.z);

            e1 = __expf(a[j].w); e2 = __expf(v[j].w);
            S1.w += e1; S2.w += e2;
            S11.w = fmaf(e1, e1, S11.w); S22.w = fmaf(e2, e2, S22.w);
            S12.w = fmaf(e1, e2, S12.w);
        }
    }

    const int4 mg = __ldg(&((const int4*)margin)[t]);

    float local = finalize_pixel(S1.x, S2.x, S11.x, S22.x, S12.x, mg.x)
                + finalize_pixel(S1.y, S2.y, S11.y, S22.y, S12.y, mg.y)
                + finalize_pixel(S1.z, S2.z, S11.z, S22.z, S12.z, mg.z)
                + finalize_pixel(S1.w, S2.w, S11.w, S22.w, S12.w, mg.w);

    // warp reduce
#pragma unroll
    for (int off = 16; off > 0; off >>= 1)
        local += __shfl_xor_sync(0xFFFFFFFF, local, off);

    __shared__ float warp_sums[BLOCK_SIZE / 32];
    const int lane = threadIdx.x & 31;
    const int wid  = threadIdx.x >> 5;
    if (lane == 0) warp_sums[wid] = local;
    __syncthreads();

    __shared__ bool is_last;
    if (threadIdx.x == 0) {
        float s = warp_sums[0];
#pragma unroll
        for (int w = 1; w < BLOCK_SIZE / 32; w++) s += warp_sums[w];
        atomicAdd(&g_acc, s);
        __threadfence();
        unsigned prev = atomicAdd(&g_count, 1u);
        is_last = (prev == (unsigned)(NBLOCKS - 1));
    }
    __syncthreads();

    if (is_last && threadIdx.x == 0) {
        __threadfence();  // make all g_acc contributions visible
        float total = *((volatile float*)&g_acc);
        out[0] = total * (1.0f / (float)NPIX);
        // reset for next graph replay (deterministic relaunch)
        g_acc   = 0.0f;
        g_count = 0u;
    }
}

extern "C" void kernel_launch(void* const* d_in, const int* in_sizes, int n_in,
                              void* d_out, int out_size) {
    const float* x1     = (const float*)d_in[0];
    const float* x2     = (const float*)d_in[1];
    const int*   margin = (const int*)d_in[2];
    float* out = (float*)d_out;

    pearson_loss_kernel<<<NBLOCKS, BLOCK_SIZE>>>(x1, x2, margin, out);
}

// round 16
// speedup vs baseline: 1.2268x; 1.0202x over previous
#include <cuda_runtime.h>
#include <cuda_bf16.h>

// PearsonLoss: x1 [8,32,256,256] f32, x2 same, margin [8,256,256] i32 -> scalar f32
//
// FINAL (confirmed lock-in; best measured 27.49us bench on this exact source,
// R5 twin measured 28.13us -> run-to-run noise band ~0.6-1.0us).
//
// Streaming formulation over C=32 channels (no probability storage):
//   e1=exp(x1), e2=exp(x2); S1,S2,S11,S22,S12 running sums.
//   EX=EY=1/C exactly (softmax sums to 1).
//   score = (S12/(S1*S2*C) - 1/C^2) / sqrt((S11/(S1^2 C)-1/C^2)(S22/(S2^2 C)-1/C^2))
//   per_pixel = margin==0 ? 1-score : max(score,0);  out = mean.
//
// Session evidence (11 measurements): the ~5.2TB/s DRAM plateau is invariant
// to occupancy (up 2x / down 3.5x), MLP batching, block shape, channel-order
// desync, and cache flavor (.ca/.cs/.cv); narrower loads, smem pipelining,
// and L2 prefetch all regressed (2x / +40% / +17%). ~26.5-27.5us kernel is
// this workload's floor on this part. Committed configuration:
//  - BLOCK=128, 4px/thread, grid 1024; group-of-4-channel batched float4
//    __ldcs loads; launch_bounds(128,7).
//  - Single launch; last-block-done finalize via __device__ globals, reset
//    by the final block for deterministic graph replay.

#define C_CH   32
#define HW     65536          // 256*256
#define NBATCH 8
#define NPIX   (NBATCH * HW)  // 524288
#define PIX_PER_THREAD 4
#define NTHREADS_TOTAL (NPIX / PIX_PER_THREAD)  // 131072
#define BLOCK_SIZE 128
#define NBLOCKS (NTHREADS_TOTAL / BLOCK_SIZE)   // 1024
#define CH_GROUP 4
#define N_GROUPS (C_CH / CH_GROUP)              // 8

__device__ float        g_acc   = 0.0f;
__device__ unsigned int g_count = 0u;

__device__ __forceinline__ float finalize_pixel(float s1, float s2,
                                                float s11, float s22, float s12,
                                                int m) {
    const float invC  = 1.0f / 32.0f;
    const float invC2 = invC * invC;
    float r1 = __frcp_rn(s1);
    float r2 = __frcp_rn(s2);
    float vx  = fmaf(s11 * r1 * r1, invC, -invC2);   // EX2 - EX^2
    float vy  = fmaf(s22 * r2 * r2, invC, -invC2);   // EY2 - EY^2
    float num = fmaf(s12 * r1 * r2, invC, -invC2);   // EXY - EX*EY
    float score = num * rsqrtf(vx * vy);
    return (m == 0) ? (1.0f - score) : fmaxf(score, 0.0f);
}

__global__ void __launch_bounds__(BLOCK_SIZE, 7)
pearson_loss_kernel(const float* __restrict__ x1,
                    const float* __restrict__ x2,
                    const int*   __restrict__ margin,
                    float* __restrict__ out) {
    const int t  = blockIdx.x * BLOCK_SIZE + threadIdx.x;  // 0..131071
    const int p0 = t * PIX_PER_THREAD;                     // base pixel
    const int b  = p0 >> 16;                               // / HW
    const int hw = p0 & (HW - 1);

    const float4* __restrict__ x1p =
        (const float4*)(x1 + (size_t)b * C_CH * HW + hw);
    const float4* __restrict__ x2p =
        (const float4*)(x2 + (size_t)b * C_CH * HW + hw);
    const int cstride4 = HW / 4;   // float4 stride per channel

    float4 S1  = make_float4(0.f, 0.f, 0.f, 0.f);
    float4 S2  = make_float4(0.f, 0.f, 0.f, 0.f);
    float4 S11 = make_float4(0.f, 0.f, 0.f, 0.f);
    float4 S22 = make_float4(0.f, 0.f, 0.f, 0.f);
    float4 S12 = make_float4(0.f, 0.f, 0.f, 0.f);

#pragma unroll
    for (int g = 0; g < N_GROUPS; g++) {
        // Batch-issue all 8 loads of this group before any compute.
        float4 a[CH_GROUP], v[CH_GROUP];
#pragma unroll
        for (int j = 0; j < CH_GROUP; j++) {
            const int c = g * CH_GROUP + j;
            a[j] = __ldcs(&x1p[c * cstride4]);
            v[j] = __ldcs(&x2p[c * cstride4]);
        }
#pragma unroll
        for (int j = 0; j < CH_GROUP; j++) {
            float e1, e2;
            e1 = __expf(a[j].x); e2 = __expf(v[j].x);
            S1.x += e1; S2.x += e2;
            S11.x = fmaf(e1, e1, S11.x); S22.x = fmaf(e2, e2, S22.x);
            S12.x = fmaf(e1, e2, S12.x);

            e1 = __expf(a[j].y); e2 = __expf(v[j].y);
            S1.y += e1; S2.y += e2;
            S11.y = fmaf(e1, e1, S11.y); S22.y = fmaf(e2, e2, S22.y);
            S12.y = fmaf(e1, e2, S12.y);

            e1 = __expf(a[j].z); e2 = __expf(v[j].z);
            S1.z += e1; S2.z += e2;
            S11.z = fmaf(e1, e1, S11.z); S22.z = fmaf(e2, e2, S22.z);
            S12.z = fmaf(e1, e2, S12.z);

            e1 = __expf(a[j].w); e2 = __expf(v[j].w);
            S1.w += e1; S2.w += e2;
            S11.w = fmaf(e1, e1, S11.w); S22.w = fmaf(e2, e2, S22.w);
            S12.w = fmaf(e1, e2, S12.w);
        }
    }

    const int4 mg = __ldg(&((const int4*)margin)[t]);

    float local = finalize_pixel(S1.x, S2.x, S11.x, S22.x, S12.x, mg.x)
                + finalize_pixel(S1.y, S2.y, S11.y, S22.y, S12.y, mg.y)
                + finalize_pixel(S1.z, S2.z, S11.z, S22.z, S12.z, mg.z)
                + finalize_pixel(S1.w, S2.w, S11.w, S22.w, S12.w, mg.w);

    // warp reduce
#pragma unroll
    for (int off = 16; off > 0; off >>= 1)
        local += __shfl_xor_sync(0xFFFFFFFF, local, off);

    __shared__ float warp_sums[BLOCK_SIZE / 32];
    const int lane = threadIdx.x & 31;
    const int wid  = threadIdx.x >> 5;
    if (lane == 0) warp_sums[wid] = local;
    __syncthreads();

    __shared__ bool is_last;
    if (threadIdx.x == 0) {
        float s = warp_sums[0];
#pragma unroll
        for (int w = 1; w < BLOCK_SIZE / 32; w++) s += warp_sums[w];
        atomicAdd(&g_acc, s);
        __threadfence();
        unsigned prev = atomicAdd(&g_count, 1u);
        is_last = (prev == (unsigned)(NBLOCKS - 1));
    }
    __syncthreads();

    if (is_last && threadIdx.x == 0) {
        __threadfence();  // make all g_acc contributions visible
        float total = *((volatile float*)&g_acc);
        out[0] = total * (1.0f / (float)NPIX);
        // reset for next graph replay (deterministic relaunch)
        g_acc   = 0.0f;
        g_count = 0u;
    }
}

extern "C" void kernel_launch(void* const* d_in, const int* in_sizes, int n_in,
                              void* d_out, int out_size) {
    const float* x1     = (const float*)d_in[0];
    const float* x2     = (const float*)d_in[1];
    const int*   margin = (const int*)d_in[2];
    float* out = (float*)d_out;

    pearson_loss_kernel<<<NBLOCKS, BLOCK_SIZE>>>(x1, x2, margin, out);
}